// round 1
// baseline (speedup 1.0000x reference)
#include <cuda_runtime.h>
#include <math_constants.h>

// Shapes (fixed by the problem)
#define kB 8
#define kN 512
#define kF 128
#define kH 4
#define kC 64
#define OUTW (2*kH*kC)   // 512

// Scratch (device globals: allocation-free)
__device__ float g_feats[kB*kH*kN*kC];   // [b][h][n][c]
__device__ float g_as[kB*kH*kN];
__device__ float g_an[kB*kH*kN];

// ---------------------------------------------------------------------------
// Kernel 1: feats = X @ kernels[h]  (64x64 tile per CTA, K=128)
// also: a_s[i] = feats[i,:].attn_self ; a_n[i] = feats[i,:].attn_neigh
// also: out[b,n, h*64+c] = relu(feats)   (the "emb" half of the concat)
// ---------------------------------------------------------------------------
extern "C" __global__ void __launch_bounds__(256)
proj_kernel(const float* __restrict__ X, const float* __restrict__ Wk,
            const float* __restrict__ a_self, const float* __restrict__ a_neigh,
            float* __restrict__ out)
{
    extern __shared__ float sm[];
    float (*Xs)[129] = (float(*)[129])sm;              // 64 x 129 (pad 1)
    float (*Ks)[68]  = (float(*)[68])(sm + 64*129);    // 128 x 68 (pad 4, float4-ok)

    const int bid  = blockIdx.x;
    const int rb   = bid & 7;
    const int h    = (bid >> 3) & 3;
    const int b    = bid >> 5;
    const int row0 = rb * 64;
    const int t    = threadIdx.x;

    for (int idx = t; idx < 64*128; idx += 256) {
        int r = idx >> 7, f = idx & 127;
        Xs[r][f] = X[(size_t)(b*kN + row0 + r)*kF + f];
    }
    for (int idx = t; idx < 128*64; idx += 256) {
        int f = idx >> 6, c = idx & 63;
        Ks[f][c] = Wk[(h*kF + f)*kC + c];
    }
    __syncthreads();

    const int tx = t & 15, ty = t >> 4;
    float acc[4][4] = {};
    #pragma unroll 4
    for (int k = 0; k < 128; ++k) {
        float a0 = Xs[ty*4+0][k];
        float a1 = Xs[ty*4+1][k];
        float a2 = Xs[ty*4+2][k];
        float a3 = Xs[ty*4+3][k];
        float4 bv = *(const float4*)&Ks[k][tx*4];
        acc[0][0] += a0*bv.x; acc[0][1] += a0*bv.y; acc[0][2] += a0*bv.z; acc[0][3] += a0*bv.w;
        acc[1][0] += a1*bv.x; acc[1][1] += a1*bv.y; acc[1][2] += a1*bv.z; acc[1][3] += a1*bv.w;
        acc[2][0] += a2*bv.x; acc[2][1] += a2*bv.y; acc[2][2] += a2*bv.z; acc[2][3] += a2*bv.w;
        acc[3][0] += a3*bv.x; acc[3][1] += a3*bv.y; acc[3][2] += a3*bv.z; acc[3][3] += a3*bv.w;
    }

    const float4 ws = *(const float4*)&a_self[h*kC + tx*4];
    const float4 wn = *(const float4*)&a_neigh[h*kC + tx*4];

    #pragma unroll
    for (int i = 0; i < 4; ++i) {
        const int r = row0 + ty*4 + i;
        float4 v = make_float4(acc[i][0], acc[i][1], acc[i][2], acc[i][3]);
        *(float4*)&g_feats[((size_t)(b*kH + h)*kN + r)*kC + tx*4] = v;
        float4 rv = make_float4(fmaxf(v.x,0.f), fmaxf(v.y,0.f), fmaxf(v.z,0.f), fmaxf(v.w,0.f));
        *(float4*)&out[((size_t)(b*kN) + r)*OUTW + h*kC + tx*4] = rv;

        float ps = v.x*ws.x + v.y*ws.y + v.z*ws.z + v.w*ws.w;
        float pn = v.x*wn.x + v.y*wn.y + v.z*wn.z + v.w*wn.w;
        // reduce across the 16 tx lanes (lane = (ty&1)*16 + tx; xor 1,2,4,8 stays in group)
        #pragma unroll
        for (int d = 8; d >= 1; d >>= 1) {
            ps += __shfl_xor_sync(0xffffffffu, ps, d);
            pn += __shfl_xor_sync(0xffffffffu, pn, d);
        }
        if (tx == 0) {
            g_as[(b*kH + h)*kN + r] = ps;
            g_an[(b*kH + h)*kN + r] = pn;
        }
    }
}

// ---------------------------------------------------------------------------
// Kernel 2: per (b,h,64-row tile): flash-style masked softmax + P @ feats.
// coef[i,j] = lrelu(a_s[i]+a_n[j]); masked (A==0) -> -inf -> exp==0 exactly,
// matching the reference's exp(x - 1e10 - max) underflow to 0.
// out[b,n, 256 + h*64+c] = relu(P@feats + bias)   (the "agg" half; see theory)
// ---------------------------------------------------------------------------
extern "C" __global__ void __launch_bounds__(256)
attn_kernel(const float* __restrict__ A, const float* __restrict__ biases,
            float* __restrict__ out)
{
    extern __shared__ float sm[];
    float (*Fs)[68] = (float(*)[68])sm;                // 128 x 68 : feats chunk [j][c]
    float (*Pt)[68] = (float(*)[68])(sm + 128*68);     // 128 x 68 : P transposed [j][i]
    float* ans     = sm + 2*128*68;                    // 128
    float* scale_s = ans + 128;                        // 64
    float* l_s     = scale_s + 64;                     // 64

    const int bid  = blockIdx.x;
    const int rb   = bid & 7;
    const int h    = (bid >> 3) & 3;
    const int b    = bid >> 5;
    const int row0 = rb * 64;
    const int t    = threadIdx.x;

    // P-phase mapping: 4 threads per row, 32 contiguous j's each
    const int ip = t >> 2, q = t & 3;
    const int gi = row0 + ip;
    const float a_s = g_as[(b*kH + h)*kN + gi];
    const float* Arow  = A + ((size_t)b*kN + gi)*kN;
    const float* fbase = g_feats + (size_t)(b*kH + h)*kN*kC;
    const float* anb   = g_an + (b*kH + h)*kN;

    // GEMM-phase mapping
    const int tx = t & 15, ty = t >> 4;
    float acc[4][4] = {};
    float m = -CUDART_INF_F, l = 0.f;
    const float NEG_INF = -CUDART_INF_F;

    for (int ch = 0; ch < 4; ++ch) {
        const int j0 = ch * 128;

        for (int idx = t; idx < 128*64; idx += 256) {
            int j = idx >> 6, c = idx & 63;
            Fs[j][c] = fbase[(size_t)(j0 + j)*kC + c];
        }
        if (t < 128) ans[t] = anb[j0 + t];
        __syncthreads();

        // pass 1: masked leaky-relu logits -> Pt, track chunk max
        float cmax = NEG_INF;
        const int jj0 = q * 32;
        #pragma unroll
        for (int s = 0; s < 32; s += 4) {
            float4 av = *(const float4*)&Arow[j0 + jj0 + s];
            float aa[4] = {av.x, av.y, av.z, av.w};
            #pragma unroll
            for (int k2 = 0; k2 < 4; ++k2) {
                float e = a_s + ans[jj0 + s + k2];
                e = (e > 0.f) ? e : 0.2f * e;
                e = (aa[k2] != 0.f) ? e : NEG_INF;
                cmax = fmaxf(cmax, e);
                Pt[jj0 + s + k2][ip] = e;
            }
        }
        cmax = fmaxf(cmax, __shfl_xor_sync(0xffffffffu, cmax, 1));
        cmax = fmaxf(cmax, __shfl_xor_sync(0xffffffffu, cmax, 2));
        float mnew = fmaxf(m, cmax);
        float mc   = fmaxf(mnew, -1e30f);               // finite for exp math
        float scale = __expf(fmaxf(m, -1e30f) - mc);
        m = mnew;

        // pass 2: exponentiate in place, row-sum
        float ls = 0.f;
        #pragma unroll
        for (int s = 0; s < 32; ++s) {
            float p = __expf(Pt[jj0 + s][ip] - mc);     // -inf -> 0 exactly
            Pt[jj0 + s][ip] = p;
            ls += p;
        }
        ls += __shfl_xor_sync(0xffffffffu, ls, 1);
        ls += __shfl_xor_sync(0xffffffffu, ls, 2);
        l = l * scale + ls;
        if (q == 0) scale_s[ip] = scale;
        __syncthreads();

        // GEMM phase: rescale accumulators, then acc += P(64x128) @ Fs(128x64)
        float sc0 = scale_s[ty*4+0], sc1 = scale_s[ty*4+1];
        float sc2 = scale_s[ty*4+2], sc3 = scale_s[ty*4+3];
        #pragma unroll
        for (int j = 0; j < 4; ++j) { acc[0][j]*=sc0; acc[1][j]*=sc1; acc[2][j]*=sc2; acc[3][j]*=sc3; }

        #pragma unroll 4
        for (int k = 0; k < 128; ++k) {
            float4 av = *(const float4*)&Pt[k][ty*4];
            float4 bv = *(const float4*)&Fs[k][tx*4];
            acc[0][0] += av.x*bv.x; acc[0][1] += av.x*bv.y; acc[0][2] += av.x*bv.z; acc[0][3] += av.x*bv.w;
            acc[1][0] += av.y*bv.x; acc[1][1] += av.y*bv.y; acc[1][2] += av.y*bv.z; acc[1][3] += av.y*bv.w;
            acc[2][0] += av.z*bv.x; acc[2][1] += av.z*bv.y; acc[2][2] += av.z*bv.z; acc[2][3] += av.z*bv.w;
            acc[3][0] += av.w*bv.x; acc[3][1] += av.w*bv.y; acc[3][2] += av.w*bv.z; acc[3][3] += av.w*bv.w;
        }
        __syncthreads();
    }

    if (q == 0) l_s[ip] = l;
    __syncthreads();

    const float4 bias = *(const float4*)&biases[h*kC + tx*4];
    #pragma unroll
    for (int i = 0; i < 4; ++i) {
        const int r = row0 + ty*4 + i;
        const float inv = 1.0f / l_s[ty*4 + i];
        float4 o;
        o.x = fmaxf(acc[i][0]*inv + bias.x, 0.f);
        o.y = fmaxf(acc[i][1]*inv + bias.y, 0.f);
        o.z = fmaxf(acc[i][2]*inv + bias.z, 0.f);
        o.w = fmaxf(acc[i][3]*inv + bias.w, 0.f);
        *(float4*)&out[((size_t)(b*kN) + r)*OUTW + kH*kC + h*kC + tx*4] = o;
    }
}

// ---------------------------------------------------------------------------
extern "C" void kernel_launch(void* const* d_in, const int* in_sizes, int n_in,
                              void* d_out, int out_size)
{
    const float* X       = (const float*)d_in[0];
    const float* A       = (const float*)d_in[1];
    const float* Wk      = (const float*)d_in[2];
    const float* biases  = (const float*)d_in[3];
    const float* a_self  = (const float*)d_in[4];
    const float* a_neigh = (const float*)d_in[5];
    float* out = (float*)d_out;

    const int PROJ_SMEM = (64*129 + 128*68) * 4;                    // 67840 B
    const int ATTN_SMEM = (2*128*68 + 128 + 64 + 64) * 4;           // 70656 B

    cudaFuncSetAttribute(proj_kernel, cudaFuncAttributeMaxDynamicSharedMemorySize, PROJ_SMEM);
    cudaFuncSetAttribute(attn_kernel, cudaFuncAttributeMaxDynamicSharedMemorySize, ATTN_SMEM);

    proj_kernel<<<kB*kH*8, 256, PROJ_SMEM>>>(X, Wk, a_self, a_neigh, out);
    attn_kernel<<<kB*kH*8, 256, ATTN_SMEM>>>(A, biases, out);
}

// round 2
// speedup vs baseline: 1.8861x; 1.8861x over previous
#include <cuda_runtime.h>
#include <math_constants.h>

// Shapes (fixed by the problem)
#define kB 8
#define kN 512
#define kF 128
#define kH 4
#define kC 64
#define OUTW (2*kH*kC)   // 512

// Scratch (device globals: allocation-free)
__device__ float g_feats[kB*kH*kN*kC];   // [b][h][n][c]
__device__ float g_as[kB*kH*kN];
__device__ float g_an[kB*kH*kN];

// ---------------------------------------------------------------------------
// Kernel 1: feats = X @ kernels[h]  (64x64 tile per CTA, K=128)
// also: a_s[i] = feats[i,:].attn_self ; a_n[i] = feats[i,:].attn_neigh
// also: out[b,n, h*64+c] = relu(feats)   (the "emb" half of the concat)
// ---------------------------------------------------------------------------
extern "C" __global__ void __launch_bounds__(256)
proj_kernel(const float* __restrict__ X, const float* __restrict__ Wk,
            const float* __restrict__ a_self, const float* __restrict__ a_neigh,
            float* __restrict__ out)
{
    extern __shared__ float sm[];
    float (*Xs)[129] = (float(*)[129])sm;              // 64 x 129 (pad 1)
    float (*Ks)[68]  = (float(*)[68])(sm + 64*129);    // 128 x 68 (pad 4, float4-ok)

    const int bid  = blockIdx.x;
    const int rb   = bid & 7;
    const int h    = (bid >> 3) & 3;
    const int b    = bid >> 5;
    const int row0 = rb * 64;
    const int t    = threadIdx.x;

    for (int idx = t; idx < 64*128; idx += 256) {
        int r = idx >> 7, f = idx & 127;
        Xs[r][f] = X[(size_t)(b*kN + row0 + r)*kF + f];
    }
    for (int idx = t; idx < 128*64; idx += 256) {
        int f = idx >> 6, c = idx & 63;
        Ks[f][c] = Wk[(h*kF + f)*kC + c];
    }
    __syncthreads();

    const int tx = t & 15, ty = t >> 4;
    float acc[4][4] = {};
    #pragma unroll 4
    for (int k = 0; k < 128; ++k) {
        float a0 = Xs[ty*4+0][k];
        float a1 = Xs[ty*4+1][k];
        float a2 = Xs[ty*4+2][k];
        float a3 = Xs[ty*4+3][k];
        float4 bv = *(const float4*)&Ks[k][tx*4];
        acc[0][0] += a0*bv.x; acc[0][1] += a0*bv.y; acc[0][2] += a0*bv.z; acc[0][3] += a0*bv.w;
        acc[1][0] += a1*bv.x; acc[1][1] += a1*bv.y; acc[1][2] += a1*bv.z; acc[1][3] += a1*bv.w;
        acc[2][0] += a2*bv.x; acc[2][1] += a2*bv.y; acc[2][2] += a2*bv.z; acc[2][3] += a2*bv.w;
        acc[3][0] += a3*bv.x; acc[3][1] += a3*bv.y; acc[3][2] += a3*bv.z; acc[3][3] += a3*bv.w;
    }

    const float4 ws = *(const float4*)&a_self[h*kC + tx*4];
    const float4 wn = *(const float4*)&a_neigh[h*kC + tx*4];

    #pragma unroll
    for (int i = 0; i < 4; ++i) {
        const int r = row0 + ty*4 + i;
        float4 v = make_float4(acc[i][0], acc[i][1], acc[i][2], acc[i][3]);
        *(float4*)&g_feats[((size_t)(b*kH + h)*kN + r)*kC + tx*4] = v;
        float4 rv = make_float4(fmaxf(v.x,0.f), fmaxf(v.y,0.f), fmaxf(v.z,0.f), fmaxf(v.w,0.f));
        *(float4*)&out[((size_t)(b*kN) + r)*OUTW + h*kC + tx*4] = rv;

        float ps = v.x*ws.x + v.y*ws.y + v.z*ws.z + v.w*ws.w;
        float pn = v.x*wn.x + v.y*wn.y + v.z*wn.z + v.w*wn.w;
        #pragma unroll
        for (int d = 8; d >= 1; d >>= 1) {
            ps += __shfl_xor_sync(0xffffffffu, ps, d);
            pn += __shfl_xor_sync(0xffffffffu, pn, d);
        }
        if (tx == 0) {
            g_as[(b*kH + h)*kN + r] = ps;
            g_an[(b*kH + h)*kN + r] = pn;
        }
    }
}

// ---------------------------------------------------------------------------
// Kernel 2 (SPARSE): one warp per (b, i) row.
//   1. scan A row, ballot-compact edge list (~27 edges of 512) into smem
//   2. per head: logits over edges only, softmax over edges (non-edges are
//      exactly 0 after exp, matching the reference's -1e10 underflow),
//      then acc[c] = sum_j p_j * feats[j, c]  (gather from L2-resident feats)
//   out[b,i, 256 + h*64 + c] = relu(acc/l + bias)
// ---------------------------------------------------------------------------
extern "C" __global__ void __launch_bounds__(256)
attn_sparse(const float* __restrict__ A, const float* __restrict__ biases,
            float* __restrict__ out)
{
    __shared__ unsigned short s_list[8][512];
    __shared__ float          s_val[8][512];

    const int w    = threadIdx.x >> 5;
    const int lane = threadIdx.x & 31;
    const int row  = blockIdx.x * 8 + w;      // grid = B*N/8 = 512
    const int b    = row >> 9;
    const int i    = row & 511;

    const float* Arow = A + ((size_t)b*kN + i)*kN;

    // ---- edge-list compaction (shared across heads) ----
    int nnz = 0;
    #pragma unroll
    for (int it = 0; it < 16; ++it) {
        const int j = it*32 + lane;
        const float a = Arow[j];
        const unsigned ball = __ballot_sync(0xffffffffu, a != 0.0f);
        if (a != 0.0f) {
            const int pos = nnz + __popc(ball & ((1u << lane) - 1u));
            s_list[w][pos] = (unsigned short)j;
        }
        nnz += __popc(ball);
    }
    __syncwarp();

    #pragma unroll
    for (int h = 0; h < kH; ++h) {
        const int bh = b*kH + h;
        const float a_s = g_as[bh*kN + i];
        const float* __restrict__ anb = g_an + bh*kN;
        const float* __restrict__ fb  = g_feats + (size_t)bh*kN*kC;

        // logits on edges, warp-max
        float mx = -CUDART_INF_F;
        for (int e = lane; e < nnz; e += 32) {
            const int j = s_list[w][e];
            float v = a_s + __ldg(&anb[j]);
            v = (v > 0.0f) ? v : 0.2f * v;
            s_val[w][e] = v;
            mx = fmaxf(mx, v);
        }
        #pragma unroll
        for (int d = 16; d >= 1; d >>= 1)
            mx = fmaxf(mx, __shfl_xor_sync(0xffffffffu, mx, d));

        __syncwarp();
        // exp + row sum
        float l = 0.0f;
        for (int e = lane; e < nnz; e += 32) {
            const float p = __expf(s_val[w][e] - mx);
            s_val[w][e] = p;
            l += p;
        }
        #pragma unroll
        for (int d = 16; d >= 1; d >>= 1)
            l += __shfl_xor_sync(0xffffffffu, l, d);
        __syncwarp();

        // weighted gather: each lane owns 2 channels
        float2 acc0 = make_float2(0.f, 0.f);
        float2 acc1 = make_float2(0.f, 0.f);
        int e = 0;
        for (; e + 2 <= nnz; e += 2) {
            const int   j0 = s_list[w][e];
            const int   j1 = s_list[w][e+1];
            const float p0 = s_val[w][e];
            const float p1 = s_val[w][e+1];
            const float2 f0 = *(const float2*)&fb[(size_t)j0*kC + lane*2];
            const float2 f1 = *(const float2*)&fb[(size_t)j1*kC + lane*2];
            acc0.x += p0*f0.x; acc0.y += p0*f0.y;
            acc1.x += p1*f1.x; acc1.y += p1*f1.y;
        }
        if (e < nnz) {
            const int   j0 = s_list[w][e];
            const float p0 = s_val[w][e];
            const float2 f0 = *(const float2*)&fb[(size_t)j0*kC + lane*2];
            acc0.x += p0*f0.x; acc0.y += p0*f0.y;
        }
        acc0.x += acc1.x; acc0.y += acc1.y;

        const float inv = 1.0f / l;
        const float2 bias = *(const float2*)&biases[h*kC + lane*2];
        float2 o;
        o.x = fmaxf(acc0.x*inv + bias.x, 0.0f);
        o.y = fmaxf(acc0.y*inv + bias.y, 0.0f);
        *(float2*)&out[((size_t)(b*kN) + i)*OUTW + kH*kC + h*kC + lane*2] = o;
        __syncwarp();
    }
}

// ---------------------------------------------------------------------------
extern "C" void kernel_launch(void* const* d_in, const int* in_sizes, int n_in,
                              void* d_out, int out_size)
{
    const float* X       = (const float*)d_in[0];
    const float* A       = (const float*)d_in[1];
    const float* Wk      = (const float*)d_in[2];
    const float* biases  = (const float*)d_in[3];
    const float* a_self  = (const float*)d_in[4];
    const float* a_neigh = (const float*)d_in[5];
    float* out = (float*)d_out;

    const int PROJ_SMEM = (64*129 + 128*68) * 4;                    // 67840 B

    cudaFuncSetAttribute(proj_kernel, cudaFuncAttributeMaxDynamicSharedMemorySize, PROJ_SMEM);

    proj_kernel<<<kB*kH*8, 256, PROJ_SMEM>>>(X, Wk, a_self, a_neigh, out);
    attn_sparse<<<kB*kN/8, 256>>>(A, biases, out);
}

// round 3
// speedup vs baseline: 1.9658x; 1.0423x over previous
#include <cuda_runtime.h>
#include <math_constants.h>

// Shapes (fixed by the problem)
#define kB 8
#define kN 512
#define kF 128
#define kH 4
#define kC 64
#define OUTW (2*kH*kC)   // 512

// Scratch (device globals: allocation-free)
__device__ float g_feats[kB*kH*kN*kC];   // [b][h][n][c]
__device__ float g_as[kB*kH*kN];
__device__ float g_an[kB*kH*kN];

// ---------------------------------------------------------------------------
// Kernel 1: feats = X @ kernels[h]  (32x64 tile per CTA, K=128)
// also: a_s[i] = feats[i,:].attn_self ; a_n[i] = feats[i,:].attn_neigh
// also: out[b,n, h*64+c] = relu(feats)   (the "emb" half of the concat)
// ---------------------------------------------------------------------------
extern "C" __global__ void __launch_bounds__(256)
proj_kernel(const float* __restrict__ X, const float* __restrict__ Wk,
            const float* __restrict__ a_self, const float* __restrict__ a_neigh,
            float* __restrict__ out)
{
    extern __shared__ float sm[];
    float (*Xs)[129] = (float(*)[129])sm;              // 32 x 129 (pad 1)
    float (*Ks)[68]  = (float(*)[68])(sm + 32*129);    // 128 x 68 (pad 4, float4-ok)

    const int bid  = blockIdx.x;
    const int rb   = bid & 15;
    const int h    = (bid >> 4) & 3;
    const int b    = bid >> 6;
    const int row0 = rb * 32;
    const int t    = threadIdx.x;

    for (int idx = t; idx < 32*128; idx += 256) {
        int r = idx >> 7, f = idx & 127;
        Xs[r][f] = X[(size_t)(b*kN + row0 + r)*kF + f];
    }
    for (int idx = t; idx < 128*64; idx += 256) {
        int f = idx >> 6, c = idx & 63;
        Ks[f][c] = Wk[(h*kF + f)*kC + c];
    }
    __syncthreads();

    const int tx = t & 15, ty = t >> 4;
    float acc[2][4] = {};
    #pragma unroll 4
    for (int k = 0; k < 128; ++k) {
        float a0 = Xs[ty*2+0][k];
        float a1 = Xs[ty*2+1][k];
        float4 bv = *(const float4*)&Ks[k][tx*4];
        acc[0][0] += a0*bv.x; acc[0][1] += a0*bv.y; acc[0][2] += a0*bv.z; acc[0][3] += a0*bv.w;
        acc[1][0] += a1*bv.x; acc[1][1] += a1*bv.y; acc[1][2] += a1*bv.z; acc[1][3] += a1*bv.w;
    }

    const float4 ws = *(const float4*)&a_self[h*kC + tx*4];
    const float4 wn = *(const float4*)&a_neigh[h*kC + tx*4];

    #pragma unroll
    for (int i = 0; i < 2; ++i) {
        const int r = row0 + ty*2 + i;
        float4 v = make_float4(acc[i][0], acc[i][1], acc[i][2], acc[i][3]);
        *(float4*)&g_feats[((size_t)(b*kH + h)*kN + r)*kC + tx*4] = v;
        float4 rv = make_float4(fmaxf(v.x,0.f), fmaxf(v.y,0.f), fmaxf(v.z,0.f), fmaxf(v.w,0.f));
        *(float4*)&out[((size_t)(b*kN) + r)*OUTW + h*kC + tx*4] = rv;

        float ps = v.x*ws.x + v.y*ws.y + v.z*ws.z + v.w*ws.w;
        float pn = v.x*wn.x + v.y*wn.y + v.z*wn.z + v.w*wn.w;
        #pragma unroll
        for (int d = 8; d >= 1; d >>= 1) {
            ps += __shfl_xor_sync(0xffffffffu, ps, d);
            pn += __shfl_xor_sync(0xffffffffu, pn, d);
        }
        if (tx == 0) {
            g_as[(b*kH + h)*kN + r] = ps;
            g_an[(b*kH + h)*kN + r] = pn;
        }
    }
}

// ---------------------------------------------------------------------------
// Kernel 2 (SPARSE): one warp per (b, i) row; 8 rows/CTA, all same b.
//   1. preload full A row into 16 regs (MLP=16), ballot-compact edge list
//   2. two head-PAIRS: logits/softmax for both heads at once (float2 probs),
//      gather with 4-edge x 2-head unroll (8 loads in flight)
//   non-edges are exactly 0 after exp (matches reference -1e10 underflow)
//   out[b,i, 256 + h*64 + c] = relu(acc/l + bias)
// ---------------------------------------------------------------------------
extern "C" __global__ void __launch_bounds__(256)
attn_sparse(const float* __restrict__ A, const float* __restrict__ biases,
            float* __restrict__ out)
{
    extern __shared__ float sm[];
    float*          s_an   = sm;                                   // [4][512]
    float2*         s_val  = (float2*)(sm + 2048);                 // [8][512]
    unsigned short* s_list = (unsigned short*)(sm + 2048 + 8192);  // [8][512]

    const int w    = threadIdx.x >> 5;
    const int lane = threadIdx.x & 31;
    const int row  = blockIdx.x * 8 + w;      // grid = B*N/8 = 512
    const int b    = row >> 9;
    const int i    = row & 511;

    float2*         my_val  = s_val  + (w << 9);
    unsigned short* my_list = s_list + (w << 9);

    // cache a_n for all 4 heads of this b (shared by the CTA's 8 warps)
    {
        const float* src = g_an + (size_t)b * (kH*kN);
        for (int idx = threadIdx.x; idx < kH*kN; idx += 256)
            s_an[idx] = src[idx];
    }

    // ---- preload A row (16 independent LDGs), then compact ----
    const float* Arow = A + ((size_t)b*kN + i)*kN;
    float av[16];
    #pragma unroll
    for (int it = 0; it < 16; ++it)
        av[it] = Arow[it*32 + lane];

    int nnz = 0;
    #pragma unroll
    for (int it = 0; it < 16; ++it) {
        const unsigned ball = __ballot_sync(0xffffffffu, av[it] != 0.0f);
        if (av[it] != 0.0f) {
            const int pos = nnz + __popc(ball & ((1u << lane) - 1u));
            my_list[pos] = (unsigned short)(it*32 + lane);
        }
        nnz += __popc(ball);
    }
    __syncthreads();   // s_an ready + list visible

    #pragma unroll
    for (int hp = 0; hp < 2; ++hp) {
        const int h0 = hp*2, h1 = h0 + 1;
        const int bh0 = b*kH + h0;
        const float a_s0 = g_as[bh0*kN + i];
        const float a_s1 = g_as[(bh0+1)*kN + i];
        const float* __restrict__ an0 = s_an + h0*kN;
        const float* __restrict__ an1 = s_an + h1*kN;

        // logits for both heads on edges, warp-max
        float mx0 = -CUDART_INF_F, mx1 = -CUDART_INF_F;
        for (int e = lane; e < nnz; e += 32) {
            const int j = my_list[e];
            float v0 = a_s0 + an0[j];
            float v1 = a_s1 + an1[j];
            v0 = (v0 > 0.0f) ? v0 : 0.2f * v0;
            v1 = (v1 > 0.0f) ? v1 : 0.2f * v1;
            my_val[e] = make_float2(v0, v1);
            mx0 = fmaxf(mx0, v0);
            mx1 = fmaxf(mx1, v1);
        }
        #pragma unroll
        for (int d = 16; d >= 1; d >>= 1) {
            mx0 = fmaxf(mx0, __shfl_xor_sync(0xffffffffu, mx0, d));
            mx1 = fmaxf(mx1, __shfl_xor_sync(0xffffffffu, mx1, d));
        }
        __syncwarp();

        // exp + row sums
        float l0 = 0.0f, l1 = 0.0f;
        for (int e = lane; e < nnz; e += 32) {
            float2 v = my_val[e];
            const float p0 = __expf(v.x - mx0);
            const float p1 = __expf(v.y - mx1);
            my_val[e] = make_float2(p0, p1);
            l0 += p0; l1 += p1;
        }
        #pragma unroll
        for (int d = 16; d >= 1; d >>= 1) {
            l0 += __shfl_xor_sync(0xffffffffu, l0, d);
            l1 += __shfl_xor_sync(0xffffffffu, l1, d);
        }
        __syncwarp();

        // weighted gather: lane owns 2 channels, both heads, 4-edge unroll
        const float* __restrict__ fb0 = g_feats + (size_t)bh0*kN*kC + lane*2;
        const float* __restrict__ fb1 = fb0 + kN*kC;

        float2 aA0 = {0,0}, aA1 = {0,0};   // edge slot A, heads 0/1
        float2 aB0 = {0,0}, aB1 = {0,0};   // edge slot B
        int e = 0;
        for (; e + 4 <= nnz; e += 4) {
            const int j0 = my_list[e],   j1 = my_list[e+1];
            const int j2 = my_list[e+2], j3 = my_list[e+3];
            const float2 p0 = my_val[e],   p1 = my_val[e+1];
            const float2 p2 = my_val[e+2], p3 = my_val[e+3];
            const float2 f00 = *(const float2*)&fb0[j0*kC];
            const float2 f01 = *(const float2*)&fb1[j0*kC];
            const float2 f10 = *(const float2*)&fb0[j1*kC];
            const float2 f11 = *(const float2*)&fb1[j1*kC];
            const float2 f20 = *(const float2*)&fb0[j2*kC];
            const float2 f21 = *(const float2*)&fb1[j2*kC];
            const float2 f30 = *(const float2*)&fb0[j3*kC];
            const float2 f31 = *(const float2*)&fb1[j3*kC];
            aA0.x += p0.x*f00.x; aA0.y += p0.x*f00.y;
            aA1.x += p0.y*f01.x; aA1.y += p0.y*f01.y;
            aB0.x += p1.x*f10.x; aB0.y += p1.x*f10.y;
            aB1.x += p1.y*f11.x; aB1.y += p1.y*f11.y;
            aA0.x += p2.x*f20.x; aA0.y += p2.x*f20.y;
            aA1.x += p2.y*f21.x; aA1.y += p2.y*f21.y;
            aB0.x += p3.x*f30.x; aB0.y += p3.x*f30.y;
            aB1.x += p3.y*f31.x; aB1.y += p3.y*f31.y;
        }
        for (; e < nnz; ++e) {
            const int j = my_list[e];
            const float2 p = my_val[e];
            const float2 f0 = *(const float2*)&fb0[j*kC];
            const float2 f1 = *(const float2*)&fb1[j*kC];
            aA0.x += p.x*f0.x; aA0.y += p.x*f0.y;
            aA1.x += p.y*f1.x; aA1.y += p.y*f1.y;
        }
        aA0.x += aB0.x; aA0.y += aB0.y;
        aA1.x += aB1.x; aA1.y += aB1.y;

        const float inv0 = 1.0f / l0;
        const float inv1 = 1.0f / l1;
        const float2 bias0 = *(const float2*)&biases[h0*kC + lane*2];
        const float2 bias1 = *(const float2*)&biases[h1*kC + lane*2];
        float* obase = out + ((size_t)(b*kN) + i)*OUTW + kH*kC + lane*2;
        float2 o0, o1;
        o0.x = fmaxf(aA0.x*inv0 + bias0.x, 0.0f);
        o0.y = fmaxf(aA0.y*inv0 + bias0.y, 0.0f);
        o1.x = fmaxf(aA1.x*inv1 + bias1.x, 0.0f);
        o1.y = fmaxf(aA1.y*inv1 + bias1.y, 0.0f);
        *(float2*)&obase[h0*kC] = o0;
        *(float2*)&obase[h1*kC] = o1;
        __syncwarp();
    }
}

// ---------------------------------------------------------------------------
extern "C" void kernel_launch(void* const* d_in, const int* in_sizes, int n_in,
                              void* d_out, int out_size)
{
    const float* X       = (const float*)d_in[0];
    const float* A       = (const float*)d_in[1];
    const float* Wk      = (const float*)d_in[2];
    const float* biases  = (const float*)d_in[3];
    const float* a_self  = (const float*)d_in[4];
    const float* a_neigh = (const float*)d_in[5];
    float* out = (float*)d_out;

    const int PROJ_SMEM = (32*129 + 128*68) * 4;            // 51328 B
    const int ATTN_SMEM = (2048 + 8192 + 2048) * 4;         // 49152 B

    cudaFuncSetAttribute(proj_kernel, cudaFuncAttributeMaxDynamicSharedMemorySize, PROJ_SMEM);
    cudaFuncSetAttribute(attn_sparse, cudaFuncAttributeMaxDynamicSharedMemorySize, ATTN_SMEM);

    proj_kernel<<<kB*kH*16, 256, PROJ_SMEM>>>(X, Wk, a_self, a_neigh, out);
    attn_sparse<<<kB*kN/8, 256, ATTN_SMEM>>>(A, biases, out);
}